// round 11
// baseline (speedup 1.0000x reference)
#include <cuda_runtime.h>
#include <cuda_fp16.h>
#include <cstdint>

#define N_NODES 4096
#define F_OUT   512
#define R_REL   474
#define IN_RELS 500
#define N_EDGES 131072
#define MAXDEG  512
#define MAXDUP  32
#define SCAT_BLOCKS 512
#define CONV_BLOCKS 1024
#define PRE_BLOCKS (R_REL + 4 + 1)

// ---------------- static device scratch ----------------
__device__ int      g_idx64;
__device__ int      g_count[N_NODES];
__device__ uint32_t g_bucket[N_NODES * MAXDEG];   // packed (col<<19 | key)
__device__ float    g_s[R_REL];
__device__ float    g_rv[N_EDGES];                // relu(score) per edge
__device__ __half   g_in_h[N_NODES * F_OUT];      // fp16 copy of input (4MB)

// ---------------- pre: scores + zero + detect ----------------
__global__ __launch_bounds__(256) void k_pre(const float* __restrict__ rel,
                                             const float* __restrict__ w_rel,
                                             const void* __restrict__ edge_src) {
    int b = blockIdx.x;
    int t = threadIdx.x;
    if (b < R_REL) {
        __shared__ float s_red[8];
        float acc = 0.f;
        if (t < 125) {
            float4 v = __ldg(((const float4*)(rel + (size_t)b * IN_RELS)) + t);
            float4 w = __ldg(((const float4*)w_rel) + t);
            acc = v.x * w.x + v.y * w.y + v.z * w.z + v.w * w.w;
        }
        for (int o = 16; o; o >>= 1) acc += __shfl_down_sync(0xffffffffu, acc, o);
        if ((t & 31) == 0) s_red[t >> 5] = acc;
        __syncthreads();
        if (t == 0) g_s[b] = s_red[0] + s_red[1] + s_red[2] + s_red[3] +
                             s_red[4] + s_red[5] + s_red[6] + s_red[7];
    } else if (b < R_REL + 4) {
        int base = (b - R_REL) * 1024 + t;
        #pragma unroll
        for (int i = 0; i < 4; i++) g_count[base + i * 256] = 0;
    } else {
        const int* w = (const int*)edge_src;
        int bad = (w[2 * t + 1] != 0);
        int any = __syncthreads_or(bad);
        if (t == 0) g_idx64 = !any;
    }
}

// ---------------- fp32 -> fp16 convert of input ----------------
__global__ __launch_bounds__(256) void k_conv(const float* __restrict__ input) {
    int g = blockIdx.x * 256 + threadIdx.x;
    const float4* in4 = (const float4*)input;
    uint2* out2 = (uint2*)g_in_h;
    #pragma unroll
    for (int i = 0; i < 2; i++) {
        int idx = g + i * 262144;
        float4 v = in4[idx];
        __half2 lo = __floats2half2_rn(v.x, v.y);
        __half2 hi = __floats2half2_rn(v.z, v.w);
        uint2 p;
        p.x = *(uint32_t*)&lo;
        p.y = *(uint32_t*)&hi;
        out2[idx] = p;
    }
}

// ---------------- scatter edges into per-row buckets ----------------
// priority replicates the reference's sequential scatters:
//   phase1 (src,dst) key=e+1; phase2 (dst,src) key=E+e+1; larger key wins
__global__ __launch_bounds__(256) void k_scatter(const void* __restrict__ esrc,
                                                 const void* __restrict__ edst,
                                                 const void* __restrict__ ridx) {
    int e = blockIdx.x * 256 + threadIdx.x;
    int src, dst, r;
    if (g_idx64) {
        src = (int)((const long long*)esrc)[e];
        dst = (int)((const long long*)edst)[e];
        r   = (int)((const long long*)ridx)[e];
    } else {
        src = ((const int*)esrc)[e];
        dst = ((const int*)edst)[e];
        r   = ((const int*)ridx)[e];
    }
    float v = g_s[r];
    g_rv[e] = v > 0.f ? v : 0.f;

    uint32_t p1 = ((uint32_t)dst << 19) | (uint32_t)(e + 1);
    int pos1 = atomicAdd(&g_count[src], 1);
    if (pos1 < MAXDEG) g_bucket[src * MAXDEG + pos1] = p1;

    uint32_t p2 = ((uint32_t)src << 19) | (uint32_t)(N_EDGES + e + 1);
    int pos2 = atomicAdd(&g_count[dst], 1);
    if (pos2 < MAXDEG) g_bucket[dst * MAXDEG + pos2] = p2;
}

// ---------------- per-row: 3-barrier prologue, unnormalized HFMA2 gather ----------
__global__ __launch_bounds__(128) void k_row(const float* __restrict__ bias,
                                             float* __restrict__ out) {
    __shared__ uint32_t sp[MAXDEG];       // packed entries (for rare dup scans)
    __shared__ float    slog[MAXDEG];     // logits
    __shared__ uint2    cw[MAXDEG + 8];   // (row byte offset, UNNORMALIZED w half2)
    __shared__ uint32_t bits[128];        // 4096-bit column-seen bitmap
    __shared__ int      s_dupcols[MAXDUP];
    __shared__ int      s_ndup;
    __shared__ float    s_red[4];

    int row = blockIdx.x;
    int t = threadIdx.x;
    int cnt = g_count[row];
    if (cnt > MAXDEG) cnt = MAXDEG;

    bits[t] = 0;
    if (t == 0) s_ndup = 0;
    __syncthreads();                                     // barrier A

    // pass 1: load entries, bitmap-flag duplicate columns, fetch logits
    for (int k = t; k < cnt; k += 128) {
        uint32_t p = g_bucket[row * MAXDEG + k];
        sp[k] = p;
        uint32_t c = p >> 19;
        uint32_t bit = 1u << (c & 31);
        uint32_t old = atomicOr(&bits[c >> 5], bit);
        if (old & bit) {
            int q = atomicAdd(&s_ndup, 1);
            if (q < MAXDUP) s_dupcols[q] = (int)c;
        }
        int e = (int)(p & 0x7FFFFu) - 1;
        if (e >= N_EDGES) e -= N_EDGES;
        slog[k] = g_rv[e];
    }
    __syncthreads();                                     // barrier B

    int ndup = s_ndup; if (ndup > MAXDUP) ndup = MAXDUP;
    bool hasdiag = (bits[row >> 5] >> (row & 31)) & 1u;  // same answer in all threads
    int nv = cnt + (hasdiag ? 0 : 1);

    // pass 2: resolve dups, exp (no max-shift: logits in [0,~6], stable),
    // pack unnormalized fp16 weights, accumulate partial sum
    float psum = 0.f;
    for (int k = t; k < cnt; k += 128) {
        uint32_t p = sp[k];
        uint32_t c = p >> 19;
        bool loser = false;
        if (ndup) {
            bool isdup = false;
            for (int j = 0; j < ndup; j++) isdup |= (s_dupcols[j] == (int)c);
            if (isdup) {
                for (int j = 0; j < cnt; j++) {
                    uint32_t q = sp[j];
                    if ((q >> 19) == c && q > p) { loser = true; break; }
                }
            }
        }
        float w = loser ? 0.f : expf(slog[k]);
        psum += w;
        __half2 wh = __float2half2_rn(w);
        cw[k] = make_uint2(c * 1024u, *(uint32_t*)&wh);
    }
    if (!hasdiag && t == 0) {                            // diagonal: exp(0) = 1
        __half2 one = __float2half2_rn(1.f);
        cw[cnt] = make_uint2((uint32_t)row * 1024u, *(uint32_t*)&one);
        psum += 1.f;
    }
    for (int o = 16; o; o >>= 1) psum += __shfl_xor_sync(0xffffffffu, psum, o);
    if ((t & 31) == 0) s_red[t >> 5] = psum;
    __syncthreads();                                     // barrier C
    float inv = 1.f / (s_red[0] + s_red[1] + s_red[2] + s_red[3]);

    // gather: thread t owns cols 4t..4t+3; depth-8 batches with cw-prefetch;
    // fp16 HFMA2 accumulation (unnormalized), flushed to fp32 every 4 neighbors.
    const char* base = ((const char*)g_in_h) + t * 8;
    float4 sum = make_float4(0.f, 0.f, 0.f, 0.f);
    float4 bv = __ldg(((const float4*)bias) + t);

    uint32_t off[8], wbits[8];
    if (nv >= 8) {
        #pragma unroll
        for (int j = 0; j < 8; j++) { uint2 ee = cw[j]; off[j] = ee.x; wbits[j] = ee.y; }
    }
    int k = 0;
    for (; k + 8 <= nv; k += 8) {
        uint2 a[8];
        #pragma unroll
        for (int j = 0; j < 8; j++) a[j] = *(const uint2*)(base + off[j]);
        uint32_t noff[8], nw[8];
        bool more = (k + 16 <= nv);
        if (more) {
            #pragma unroll
            for (int j = 0; j < 8; j++) { uint2 ee = cw[k + 8 + j]; noff[j] = ee.x; nw[j] = ee.y; }
        }
        #pragma unroll
        for (int g = 0; g < 2; g++) {
            __half2 h0 = __float2half2_rn(0.f);
            __half2 h1 = __float2half2_rn(0.f);
            #pragma unroll
            for (int j = 4 * g; j < 4 * g + 4; j++) {
                __half2 w2 = *(__half2*)&wbits[j];
                h0 = __hfma2(w2, *(__half2*)&a[j].x, h0);
                h1 = __hfma2(w2, *(__half2*)&a[j].y, h1);
            }
            float2 f0 = __half22float2(h0);
            float2 f1 = __half22float2(h1);
            sum.x += f0.x; sum.y += f0.y;
            sum.z += f1.x; sum.w += f1.y;
        }
        if (more) {
            #pragma unroll
            for (int j = 0; j < 8; j++) { off[j] = noff[j]; wbits[j] = nw[j]; }
        }
    }
    for (; k < nv; k++) {           // tail: fp32 path (w already half-quantized)
        uint2 ee = cw[k];
        uint2 aa = *(const uint2*)(base + ee.x);
        float w = __low2float(*(__half2*)&ee.y);
        float2 lo = __half22float2(*(__half2*)&aa.x);
        float2 hi = __half22float2(*(__half2*)&aa.y);
        sum.x += w * lo.x; sum.y += w * lo.y;
        sum.z += w * hi.x; sum.w += w * hi.y;
    }

    // normalize, add bias, elu (alpha=1)
    float4 acc;
    acc.x = fmaf(sum.x, inv, bv.x);
    acc.y = fmaf(sum.y, inv, bv.y);
    acc.z = fmaf(sum.z, inv, bv.z);
    acc.w = fmaf(sum.w, inv, bv.w);
    acc.x = acc.x > 0.f ? acc.x : expm1f(acc.x);
    acc.y = acc.y > 0.f ? acc.y : expm1f(acc.y);
    acc.z = acc.z > 0.f ? acc.z : expm1f(acc.z);
    acc.w = acc.w > 0.f ? acc.w : expm1f(acc.w);
    ((float4*)out)[row * 128 + t] = acc;
}

// ---------------- launch ----------------
extern "C" void kernel_launch(void* const* d_in, const int* in_sizes, int n_in,
                              void* d_out, int out_size) {
    const float* input = (const float*)d_in[0];   // [4096, 512]
    const float* rel   = (const float*)d_in[1];   // [474, 500]
    const float* w_rel = (const float*)d_in[3];   // [500]
    const float* bias  = (const float*)d_in[4];   // [512]
    const void*  esrc  = d_in[5];
    const void*  edst  = d_in[6];
    const void*  ridx  = d_in[8];
    float* out = (float*)d_out;

    k_pre<<<PRE_BLOCKS, 256>>>(rel, w_rel, esrc);
    k_conv<<<CONV_BLOCKS, 256>>>(input);
    k_scatter<<<SCAT_BLOCKS, 256>>>(esrc, edst, ridx);
    k_row<<<N_NODES, 128>>>(bias, out);
}

// round 12
// speedup vs baseline: 1.1960x; 1.1960x over previous
#include <cuda_runtime.h>
#include <cuda_fp16.h>
#include <cstdint>

#define N_NODES 4096
#define F_OUT   512
#define R_REL   474
#define IN_RELS 500
#define N_EDGES 131072
#define MAXDEG  512
#define MAXDUP  32
#define SCAT_BLOCKS 512
#define CONV_BLOCKS 1024
#define PRE_BLOCKS (R_REL + 4 + 1)

// ---------------- static device scratch ----------------
__device__ int      g_idx64;
__device__ int      g_count[N_NODES];
__device__ uint32_t g_bucket[N_NODES * MAXDEG];   // packed (col<<19 | key)
__device__ float    g_s[R_REL];
__device__ float    g_rv[N_EDGES];                // relu(score) per edge
__device__ __half   g_in_h[N_NODES * F_OUT];      // fp16 copy of input (4MB)

// ---------------- pre: scores + zero + detect ----------------
__global__ __launch_bounds__(256) void k_pre(const float* __restrict__ rel,
                                             const float* __restrict__ w_rel,
                                             const void* __restrict__ edge_src) {
    int b = blockIdx.x;
    int t = threadIdx.x;
    if (b < R_REL) {
        __shared__ float s_red[8];
        float acc = 0.f;
        if (t < 125) {
            float4 v = __ldg(((const float4*)(rel + (size_t)b * IN_RELS)) + t);
            float4 w = __ldg(((const float4*)w_rel) + t);
            acc = v.x * w.x + v.y * w.y + v.z * w.z + v.w * w.w;
        }
        for (int o = 16; o; o >>= 1) acc += __shfl_down_sync(0xffffffffu, acc, o);
        if ((t & 31) == 0) s_red[t >> 5] = acc;
        __syncthreads();
        if (t == 0) g_s[b] = s_red[0] + s_red[1] + s_red[2] + s_red[3] +
                             s_red[4] + s_red[5] + s_red[6] + s_red[7];
    } else if (b < R_REL + 4) {
        int base = (b - R_REL) * 1024 + t;
        #pragma unroll
        for (int i = 0; i < 4; i++) g_count[base + i * 256] = 0;
    } else {
        const int* w = (const int*)edge_src;
        int bad = (w[2 * t + 1] != 0);
        int any = __syncthreads_or(bad);
        if (t == 0) g_idx64 = !any;
    }
}

// ---------------- fp32 -> fp16 convert of input ----------------
__global__ __launch_bounds__(256) void k_conv(const float* __restrict__ input) {
    int g = blockIdx.x * 256 + threadIdx.x;
    const float4* in4 = (const float4*)input;
    uint2* out2 = (uint2*)g_in_h;
    #pragma unroll
    for (int i = 0; i < 2; i++) {
        int idx = g + i * 262144;
        float4 v = in4[idx];
        __half2 lo = __floats2half2_rn(v.x, v.y);
        __half2 hi = __floats2half2_rn(v.z, v.w);
        uint2 p;
        p.x = *(uint32_t*)&lo;
        p.y = *(uint32_t*)&hi;
        out2[idx] = p;
    }
}

// ---------------- scatter edges into per-row buckets ----------------
// priority replicates the reference's sequential scatters:
//   phase1 (src,dst) key=e+1; phase2 (dst,src) key=E+e+1; larger key wins
__global__ __launch_bounds__(256) void k_scatter(const void* __restrict__ esrc,
                                                 const void* __restrict__ edst,
                                                 const void* __restrict__ ridx) {
    int e = blockIdx.x * 256 + threadIdx.x;
    int src, dst, r;
    if (g_idx64) {
        src = (int)((const long long*)esrc)[e];
        dst = (int)((const long long*)edst)[e];
        r   = (int)((const long long*)ridx)[e];
    } else {
        src = ((const int*)esrc)[e];
        dst = ((const int*)edst)[e];
        r   = ((const int*)ridx)[e];
    }
    float v = g_s[r];
    g_rv[e] = v > 0.f ? v : 0.f;

    uint32_t p1 = ((uint32_t)dst << 19) | (uint32_t)(e + 1);
    int pos1 = atomicAdd(&g_count[src], 1);
    if (pos1 < MAXDEG) g_bucket[src * MAXDEG + pos1] = p1;

    uint32_t p2 = ((uint32_t)src << 19) | (uint32_t)(N_EDGES + e + 1);
    int pos2 = atomicAdd(&g_count[dst], 1);
    if (pos2 < MAXDEG) g_bucket[dst * MAXDEG + pos2] = p2;
}

// ---------------- per-row: 3-barrier prologue, HFMA2 gather, occ-forced ----------
__global__ __launch_bounds__(128, 16) void k_row(const float* __restrict__ bias,
                                                 float* __restrict__ out) {
    __shared__ uint32_t sp[MAXDEG];       // packed entries (for rare dup scans)
    __shared__ float    slog[MAXDEG];     // logits
    __shared__ uint2    cw[MAXDEG + 8];   // (row byte offset, UNNORMALIZED w half2)
    __shared__ uint32_t bits[128];        // 4096-bit column-seen bitmap
    __shared__ int      s_dupcols[MAXDUP];
    __shared__ int      s_ndup;
    __shared__ float    s_red[4];

    int row = blockIdx.x;
    int t = threadIdx.x;
    int cnt = g_count[row];
    if (cnt > MAXDEG) cnt = MAXDEG;

    bits[t] = 0;
    if (t == 0) s_ndup = 0;
    __syncthreads();                                     // barrier A

    // pass 1: load entries, bitmap-flag duplicate columns, fetch logits
    for (int k = t; k < cnt; k += 128) {
        uint32_t p = g_bucket[row * MAXDEG + k];
        sp[k] = p;
        uint32_t c = p >> 19;
        uint32_t bit = 1u << (c & 31);
        uint32_t old = atomicOr(&bits[c >> 5], bit);
        if (old & bit) {
            int q = atomicAdd(&s_ndup, 1);
            if (q < MAXDUP) s_dupcols[q] = (int)c;
        }
        int e = (int)(p & 0x7FFFFu) - 1;
        if (e >= N_EDGES) e -= N_EDGES;
        slog[k] = g_rv[e];
    }
    __syncthreads();                                     // barrier B

    int ndup = s_ndup; if (ndup > MAXDUP) ndup = MAXDUP;
    bool hasdiag = (bits[row >> 5] >> (row & 31)) & 1u;  // same answer in all threads
    int nv = cnt + (hasdiag ? 0 : 1);

    // pass 2: resolve dups, exp (no max-shift: logits in [0,~6], stable),
    // pack unnormalized fp16 weights, accumulate partial sum
    float psum = 0.f;
    for (int k = t; k < cnt; k += 128) {
        uint32_t p = sp[k];
        uint32_t c = p >> 19;
        bool loser = false;
        if (ndup) {
            bool isdup = false;
            for (int j = 0; j < ndup; j++) isdup |= (s_dupcols[j] == (int)c);
            if (isdup) {
                for (int j = 0; j < cnt; j++) {
                    uint32_t q = sp[j];
                    if ((q >> 19) == c && q > p) { loser = true; break; }
                }
            }
        }
        float w = loser ? 0.f : expf(slog[k]);
        psum += w;
        __half2 wh = __float2half2_rn(w);
        cw[k] = make_uint2(c * 1024u, *(uint32_t*)&wh);
    }
    if (!hasdiag && t == 0) {                            // diagonal: exp(0) = 1
        __half2 one = __float2half2_rn(1.f);
        cw[cnt] = make_uint2((uint32_t)row * 1024u, *(uint32_t*)&one);
        psum += 1.f;
    }
    for (int o = 16; o; o >>= 1) psum += __shfl_xor_sync(0xffffffffu, psum, o);
    if ((t & 31) == 0) s_red[t >> 5] = psum;
    __syncthreads();                                     // barrier C
    float inv = 1.f / (s_red[0] + s_red[1] + s_red[2] + s_red[3]);

    // gather: thread t owns cols 4t..4t+3; depth-8 load batch from smem;
    // fp16 HFMA2 accumulation (unnormalized), flushed to fp32 every 4 neighbors.
    const char* base = ((const char*)g_in_h) + t * 8;
    float4 sum = make_float4(0.f, 0.f, 0.f, 0.f);
    float4 bv = __ldg(((const float4*)bias) + t);

    int k = 0;
    for (; k + 8 <= nv; k += 8) {
        uint2 e[8], a[8];
        #pragma unroll
        for (int j = 0; j < 8; j++) e[j] = cw[k + j];
        #pragma unroll
        for (int j = 0; j < 8; j++) a[j] = *(const uint2*)(base + e[j].x);
        #pragma unroll
        for (int g = 0; g < 2; g++) {
            __half2 h0 = __float2half2_rn(0.f);
            __half2 h1 = __float2half2_rn(0.f);
            #pragma unroll
            for (int j = 4 * g; j < 4 * g + 4; j++) {
                __half2 w2 = *(__half2*)&e[j].y;
                h0 = __hfma2(w2, *(__half2*)&a[j].x, h0);
                h1 = __hfma2(w2, *(__half2*)&a[j].y, h1);
            }
            float2 f0 = __half22float2(h0);
            float2 f1 = __half22float2(h1);
            sum.x += f0.x; sum.y += f0.y;
            sum.z += f1.x; sum.w += f1.y;
        }
    }
    for (; k < nv; k++) {           // tail: fp32 path (w already half-quantized)
        uint2 ee = cw[k];
        uint2 aa = *(const uint2*)(base + ee.x);
        float w = __low2float(*(__half2*)&ee.y);
        float2 lo = __half22float2(*(__half2*)&aa.x);
        float2 hi = __half22float2(*(__half2*)&aa.y);
        sum.x += w * lo.x; sum.y += w * lo.y;
        sum.z += w * hi.x; sum.w += w * hi.y;
    }

    // normalize, add bias, elu (alpha=1)
    float4 acc;
    acc.x = fmaf(sum.x, inv, bv.x);
    acc.y = fmaf(sum.y, inv, bv.y);
    acc.z = fmaf(sum.z, inv, bv.z);
    acc.w = fmaf(sum.w, inv, bv.w);
    acc.x = acc.x > 0.f ? acc.x : expm1f(acc.x);
    acc.y = acc.y > 0.f ? acc.y : expm1f(acc.y);
    acc.z = acc.z > 0.f ? acc.z : expm1f(acc.z);
    acc.w = acc.w > 0.f ? acc.w : expm1f(acc.w);
    ((float4*)out)[row * 128 + t] = acc;
}

// ---------------- launch ----------------
extern "C" void kernel_launch(void* const* d_in, const int* in_sizes, int n_in,
                              void* d_out, int out_size) {
    const float* input = (const float*)d_in[0];   // [4096, 512]
    const float* rel   = (const float*)d_in[1];   // [474, 500]
    const float* w_rel = (const float*)d_in[3];   // [500]
    const float* bias  = (const float*)d_in[4];   // [512]
    const void*  esrc  = d_in[5];
    const void*  edst  = d_in[6];
    const void*  ridx  = d_in[8];
    float* out = (float*)d_out;

    k_pre<<<PRE_BLOCKS, 256>>>(rel, w_rel, esrc);
    k_conv<<<CONV_BLOCKS, 256>>>(input);
    k_scatter<<<SCAT_BLOCKS, 256>>>(esrc, edst, ridx);
    k_row<<<N_NODES, 128>>>(bias, out);
}

// round 13
// speedup vs baseline: 1.2482x; 1.0436x over previous
#include <cuda_runtime.h>
#include <cuda_fp16.h>
#include <cstdint>

#define N_NODES 4096
#define F_OUT   512
#define R_REL   474
#define IN_RELS 500
#define N_EDGES 131072
#define MAXDEG  512
#define MAXDUP  32
#define SCAT_BLOCKS 512
#define CONV_BLOCKS 1024
#define INIT_BLOCKS (R_REL + 4 + 1 + CONV_BLOCKS)

// ---------------- static device scratch ----------------
__device__ int      g_idx64;
__device__ int      g_count[N_NODES];
__device__ uint2    g_bucket[N_NODES * MAXDEG];   // {(col<<19|key), half2(w,w)}
__device__ float    g_s[R_REL];
__device__ __half   g_in_h[N_NODES * F_OUT];      // fp16 copy of input (4MB)

// ---------------- init: scores + zero + detect + fp16 convert (independent) ----
// blocks [0,474): block-per-relation dot; [474,478): zero counts; 478: detect;
// [479, 479+CONV_BLOCKS): fp32 -> fp16 convert
__global__ __launch_bounds__(256) void k_init(const float* __restrict__ rel,
                                              const float* __restrict__ w_rel,
                                              const void* __restrict__ edge_src,
                                              const float* __restrict__ input) {
    int b = blockIdx.x;
    int t = threadIdx.x;
    if (b < R_REL) {
        __shared__ float s_red[8];
        float acc = 0.f;
        if (t < 125) {
            float4 v = __ldg(((const float4*)(rel + (size_t)b * IN_RELS)) + t);
            float4 w = __ldg(((const float4*)w_rel) + t);
            acc = v.x * w.x + v.y * w.y + v.z * w.z + v.w * w.w;
        }
        for (int o = 16; o; o >>= 1) acc += __shfl_down_sync(0xffffffffu, acc, o);
        if ((t & 31) == 0) s_red[t >> 5] = acc;
        __syncthreads();
        if (t == 0) g_s[b] = s_red[0] + s_red[1] + s_red[2] + s_red[3] +
                             s_red[4] + s_red[5] + s_red[6] + s_red[7];
    } else if (b < R_REL + 4) {
        int base = (b - R_REL) * 1024 + t;
        #pragma unroll
        for (int i = 0; i < 4; i++) g_count[base + i * 256] = 0;
    } else if (b == R_REL + 4) {
        // parallel dtype detect: int64 => all high words zero
        const int* w = (const int*)edge_src;
        int bad = (w[2 * t + 1] != 0);
        int any = __syncthreads_or(bad);
        if (t == 0) g_idx64 = !any;
    } else {
        int g = (b - (R_REL + 5)) * 256 + t;     // 0 .. 262143
        const float4* in4 = (const float4*)input;
        uint2* out2 = (uint2*)g_in_h;
        #pragma unroll
        for (int i = 0; i < 2; i++) {
            int idx = g + i * 262144;            // 524288 float4 total
            float4 v = in4[idx];
            __half2 lo = __floats2half2_rn(v.x, v.y);
            __half2 hi = __floats2half2_rn(v.z, v.w);
            uint2 p;
            p.x = *(uint32_t*)&lo;
            p.y = *(uint32_t*)&hi;
            out2[idx] = p;
        }
    }
}

// ---------------- scatter: weights computed here, 8B bucket entries ----------
// priority replicates the reference's sequential scatters:
//   phase1 (src,dst) key=e+1; phase2 (dst,src) key=E+e+1; larger key wins
__global__ __launch_bounds__(256) void k_scatter(const void* __restrict__ esrc,
                                                 const void* __restrict__ edst,
                                                 const void* __restrict__ ridx) {
    int e = blockIdx.x * 256 + threadIdx.x;
    int src, dst, r;
    if (g_idx64) {
        src = (int)((const long long*)esrc)[e];
        dst = (int)((const long long*)edst)[e];
        r   = (int)((const long long*)ridx)[e];
    } else {
        src = ((const int*)esrc)[e];
        dst = ((const int*)edst)[e];
        r   = ((const int*)ridx)[e];
    }
    float s = g_s[r];
    float w = expf(s > 0.f ? s : 0.f);            // exp(relu(score))
    __half2 wh = __float2half2_rn(w);
    uint32_t wbits = *(uint32_t*)&wh;

    uint2 p1 = make_uint2(((uint32_t)dst << 19) | (uint32_t)(e + 1), wbits);
    int pos1 = atomicAdd(&g_count[src], 1);
    if (pos1 < MAXDEG) g_bucket[src * MAXDEG + pos1] = p1;

    uint2 p2 = make_uint2(((uint32_t)src << 19) | (uint32_t)(N_EDGES + e + 1), wbits);
    int pos2 = atomicAdd(&g_count[dst], 1);
    if (pos2 < MAXDEG) g_bucket[dst * MAXDEG + pos2] = p2;
}

// ---------------- per-row: bitmap dedup, weight-sum, HFMA2 gather, elu --------
__global__ __launch_bounds__(128, 16) void k_row(const float* __restrict__ bias,
                                                 float* __restrict__ out) {
    __shared__ uint32_t sp[MAXDEG];       // packed (col<<19|key) for dup scans
    __shared__ uint32_t swgt[MAXDEG];     // half2 weight bits per entry
    __shared__ uint2    cw[MAXDEG + 8];   // (row byte offset, half2 weight)
    __shared__ uint32_t bits[128];        // 4096-bit column-seen bitmap
    __shared__ int      s_dupcols[MAXDUP];
    __shared__ int      s_ndup;
    __shared__ float    s_red[4];

    int row = blockIdx.x;
    int t = threadIdx.x;
    int cnt = g_count[row];
    if (cnt > MAXDEG) cnt = MAXDEG;

    bits[t] = 0;
    if (t == 0) s_ndup = 0;
    __syncthreads();                                     // barrier A

    // pass 1: load 8B entries (key + weight), bitmap-flag duplicate columns
    for (int k = t; k < cnt; k += 128) {
        uint2 e = g_bucket[row * MAXDEG + k];
        sp[k] = e.x;
        swgt[k] = e.y;
        uint32_t c = e.x >> 19;
        uint32_t bit = 1u << (c & 31);
        uint32_t old = atomicOr(&bits[c >> 5], bit);
        if (old & bit) {
            int q = atomicAdd(&s_ndup, 1);
            if (q < MAXDUP) s_dupcols[q] = (int)c;
        }
    }
    __syncthreads();                                     // barrier B

    int ndup = s_ndup; if (ndup > MAXDUP) ndup = MAXDUP;
    bool hasdiag = (bits[row >> 5] >> (row & 31)) & 1u;
    int nv = cnt + (hasdiag ? 0 : 1);

    // pass 2: zero duplicate losers, pack (offset, weight), partial weight sum
    float psum = 0.f;
    for (int k = t; k < cnt; k += 128) {
        uint32_t p = sp[k];
        uint32_t c = p >> 19;
        uint32_t wb = swgt[k];
        if (ndup) {
            bool isdup = false;
            for (int j = 0; j < ndup; j++) isdup |= (s_dupcols[j] == (int)c);
            if (isdup) {
                for (int j = 0; j < cnt; j++) {
                    uint32_t q = sp[j];
                    if ((q >> 19) == c && q > p) { wb = 0u; break; }
                }
            }
        }
        psum += __low2float(*(__half2*)&wb);
        cw[k] = make_uint2(c * 1024u, wb);
    }
    if (!hasdiag && t == 0) {                            // diagonal: exp(0) = 1
        __half2 one = __float2half2_rn(1.f);
        cw[cnt] = make_uint2((uint32_t)row * 1024u, *(uint32_t*)&one);
        psum += 1.f;
    }
    for (int o = 16; o; o >>= 1) psum += __shfl_xor_sync(0xffffffffu, psum, o);
    if ((t & 31) == 0) s_red[t >> 5] = psum;
    __syncthreads();                                     // barrier C
    float inv = 1.f / (s_red[0] + s_red[1] + s_red[2] + s_red[3]);

    // gather: thread t owns cols 4t..4t+3; depth-8 load batch from smem;
    // fp16 HFMA2 accumulation (unnormalized), flushed to fp32 every 4 neighbors.
    const char* base = ((const char*)g_in_h) + t * 8;
    float4 sum = make_float4(0.f, 0.f, 0.f, 0.f);
    float4 bv = __ldg(((const float4*)bias) + t);

    int k = 0;
    for (; k + 8 <= nv; k += 8) {
        uint2 e[8], a[8];
        #pragma unroll
        for (int j = 0; j < 8; j++) e[j] = cw[k + j];
        #pragma unroll
        for (int j = 0; j < 8; j++) a[j] = *(const uint2*)(base + e[j].x);
        #pragma unroll
        for (int g = 0; g < 2; g++) {
            __half2 h0 = __float2half2_rn(0.f);
            __half2 h1 = __float2half2_rn(0.f);
            #pragma unroll
            for (int j = 4 * g; j < 4 * g + 4; j++) {
                __half2 w2 = *(__half2*)&e[j].y;
                h0 = __hfma2(w2, *(__half2*)&a[j].x, h0);
                h1 = __hfma2(w2, *(__half2*)&a[j].y, h1);
            }
            float2 f0 = __half22float2(h0);
            float2 f1 = __half22float2(h1);
            sum.x += f0.x; sum.y += f0.y;
            sum.z += f1.x; sum.w += f1.y;
        }
    }
    for (; k < nv; k++) {           // tail: fp32 path
        uint2 ee = cw[k];
        uint2 aa = *(const uint2*)(base + ee.x);
        float w = __low2float(*(__half2*)&ee.y);
        float2 lo = __half22float2(*(__half2*)&aa.x);
        float2 hi = __half22float2(*(__half2*)&aa.y);
        sum.x += w * lo.x; sum.y += w * lo.y;
        sum.z += w * hi.x; sum.w += w * hi.y;
    }

    // normalize, add bias, elu (alpha=1)
    float4 acc;
    acc.x = fmaf(sum.x, inv, bv.x);
    acc.y = fmaf(sum.y, inv, bv.y);
    acc.z = fmaf(sum.z, inv, bv.z);
    acc.w = fmaf(sum.w, inv, bv.w);
    acc.x = acc.x > 0.f ? acc.x : expm1f(acc.x);
    acc.y = acc.y > 0.f ? acc.y : expm1f(acc.y);
    acc.z = acc.z > 0.f ? acc.z : expm1f(acc.z);
    acc.w = acc.w > 0.f ? acc.w : expm1f(acc.w);
    ((float4*)out)[row * 128 + t] = acc;
}

// ---------------- launch ----------------
extern "C" void kernel_launch(void* const* d_in, const int* in_sizes, int n_in,
                              void* d_out, int out_size) {
    const float* input = (const float*)d_in[0];   // [4096, 512]
    const float* rel   = (const float*)d_in[1];   // [474, 500]
    const float* w_rel = (const float*)d_in[3];   // [500]
    const float* bias  = (const float*)d_in[4];   // [512]
    const void*  esrc  = d_in[5];
    const void*  edst  = d_in[6];
    const void*  ridx  = d_in[8];
    float* out = (float*)d_out;

    k_init<<<INIT_BLOCKS, 256>>>(rel, w_rel, esrc, input);
    k_scatter<<<SCAT_BLOCKS, 256>>>(esrc, edst, ridx);
    k_row<<<N_NODES, 128>>>(bias, out);
}

// round 14
// speedup vs baseline: 1.3183x; 1.0562x over previous
#include <cuda_runtime.h>
#include <cuda_fp16.h>
#include <cstdint>

#define N_NODES 4096
#define F_OUT   512
#define R_REL   474
#define IN_RELS 500
#define N_EDGES 131072
#define MAXDEG  512
#define MAXDUP  32
#define SCAT_BLOCKS 512
#define CONV_BLOCKS 1024
#define INIT_BLOCKS (R_REL + 4 + 1 + CONV_BLOCKS)

// ---------------- static device scratch ----------------
__device__ int      g_idx64;
__device__ int      g_count[N_NODES];
__device__ uint2    g_bucket[N_NODES * MAXDEG];   // {(col<<19|key), half2(w,w)}
__device__ float    g_s[R_REL];
__device__ __half   g_in_h[N_NODES * F_OUT];      // fp16 copy of input (4MB)

// ---------------- init: scores + zero + detect + fp16 convert (independent) ----
__global__ __launch_bounds__(256) void k_init(const float* __restrict__ rel,
                                              const float* __restrict__ w_rel,
                                              const void* __restrict__ edge_src,
                                              const float* __restrict__ input) {
    int b = blockIdx.x;
    int t = threadIdx.x;
    if (b < R_REL) {
        __shared__ float s_red[8];
        float acc = 0.f;
        if (t < 125) {
            float4 v = __ldg(((const float4*)(rel + (size_t)b * IN_RELS)) + t);
            float4 w = __ldg(((const float4*)w_rel) + t);
            acc = v.x * w.x + v.y * w.y + v.z * w.z + v.w * w.w;
        }
        for (int o = 16; o; o >>= 1) acc += __shfl_down_sync(0xffffffffu, acc, o);
        if ((t & 31) == 0) s_red[t >> 5] = acc;
        __syncthreads();
        if (t == 0) g_s[b] = s_red[0] + s_red[1] + s_red[2] + s_red[3] +
                             s_red[4] + s_red[5] + s_red[6] + s_red[7];
    } else if (b < R_REL + 4) {
        int base = (b - R_REL) * 1024 + t;
        #pragma unroll
        for (int i = 0; i < 4; i++) g_count[base + i * 256] = 0;
    } else if (b == R_REL + 4) {
        const int* w = (const int*)edge_src;
        int bad = (w[2 * t + 1] != 0);
        int any = __syncthreads_or(bad);
        if (t == 0) g_idx64 = !any;
    } else {
        int g = (b - (R_REL + 5)) * 256 + t;
        const float4* in4 = (const float4*)input;
        uint2* out2 = (uint2*)g_in_h;
        #pragma unroll
        for (int i = 0; i < 2; i++) {
            int idx = g + i * 262144;
            float4 v = in4[idx];
            __half2 lo = __floats2half2_rn(v.x, v.y);
            __half2 hi = __floats2half2_rn(v.z, v.w);
            uint2 p;
            p.x = *(uint32_t*)&lo;
            p.y = *(uint32_t*)&hi;
            out2[idx] = p;
        }
    }
}

// ---------------- scatter: weights computed here, 8B bucket entries ----------
// priority replicates the reference's sequential scatters:
//   phase1 (src,dst) key=e+1; phase2 (dst,src) key=E+e+1; larger key wins
__global__ __launch_bounds__(256) void k_scatter(const void* __restrict__ esrc,
                                                 const void* __restrict__ edst,
                                                 const void* __restrict__ ridx) {
    int e = blockIdx.x * 256 + threadIdx.x;
    int src, dst, r;
    if (g_idx64) {
        src = (int)((const long long*)esrc)[e];
        dst = (int)((const long long*)edst)[e];
        r   = (int)((const long long*)ridx)[e];
    } else {
        src = ((const int*)esrc)[e];
        dst = ((const int*)edst)[e];
        r   = ((const int*)ridx)[e];
    }
    float s = g_s[r];
    float w = expf(s > 0.f ? s : 0.f);            // exp(relu(score))
    __half2 wh = __float2half2_rn(w);
    uint32_t wbits = *(uint32_t*)&wh;

    uint2 p1 = make_uint2(((uint32_t)dst << 19) | (uint32_t)(e + 1), wbits);
    int pos1 = atomicAdd(&g_count[src], 1);
    if (pos1 < MAXDEG) g_bucket[src * MAXDEG + pos1] = p1;

    uint2 p2 = make_uint2(((uint32_t)src << 19) | (uint32_t)(N_EDGES + e + 1), wbits);
    int pos2 = atomicAdd(&g_count[dst], 1);
    if (pos2 < MAXDEG) g_bucket[dst * MAXDEG + pos2] = p2;
}

// ---------------- per-row: 64 threads, 8 cols/thread, LDG.128 gather ----------
__global__ __launch_bounds__(64, 20) void k_row(const float* __restrict__ bias,
                                                float* __restrict__ out) {
    __shared__ uint32_t sp[MAXDEG];       // packed (col<<19|key) for dup scans
    __shared__ uint32_t swgt[MAXDEG];     // half2 weight bits per entry
    __shared__ uint2    cw[MAXDEG + 4];   // (row byte offset, half2 weight)
    __shared__ uint32_t bits[128];        // 4096-bit column-seen bitmap
    __shared__ int      s_dupcols[MAXDUP];
    __shared__ int      s_ndup;
    __shared__ float    s_red[2];

    int row = blockIdx.x;
    int t = threadIdx.x;                  // 0..63
    int cnt = g_count[row];
    if (cnt > MAXDEG) cnt = MAXDEG;

    bits[t] = 0; bits[t + 64] = 0;
    if (t == 0) s_ndup = 0;
    __syncthreads();                                     // barrier A

    // pass 1: load 8B entries, bitmap-flag duplicate columns
    for (int k = t; k < cnt; k += 64) {
        uint2 e = g_bucket[row * MAXDEG + k];
        sp[k] = e.x;
        swgt[k] = e.y;
        uint32_t c = e.x >> 19;
        uint32_t bit = 1u << (c & 31);
        uint32_t old = atomicOr(&bits[c >> 5], bit);
        if (old & bit) {
            int q = atomicAdd(&s_ndup, 1);
            if (q < MAXDUP) s_dupcols[q] = (int)c;
        }
    }
    __syncthreads();                                     // barrier B

    int ndup = s_ndup; if (ndup > MAXDUP) ndup = MAXDUP;
    bool hasdiag = (bits[row >> 5] >> (row & 31)) & 1u;
    int nv = cnt + (hasdiag ? 0 : 1);

    // pass 2: zero duplicate losers, pack (offset, weight), partial weight sum
    float psum = 0.f;
    for (int k = t; k < cnt; k += 64) {
        uint32_t p = sp[k];
        uint32_t c = p >> 19;
        uint32_t wb = swgt[k];
        if (ndup) {
            bool isdup = false;
            for (int j = 0; j < ndup; j++) isdup |= (s_dupcols[j] == (int)c);
            if (isdup) {
                for (int j = 0; j < cnt; j++) {
                    uint32_t q = sp[j];
                    if ((q >> 19) == c && q > p) { wb = 0u; break; }
                }
            }
        }
        psum += __low2float(*(__half2*)&wb);
        cw[k] = make_uint2(c * 1024u, wb);
    }
    if (!hasdiag && t == 0) {                            // diagonal: exp(0) = 1
        __half2 one = __float2half2_rn(1.f);
        cw[cnt] = make_uint2((uint32_t)row * 1024u, *(uint32_t*)&one);
        psum += 1.f;
    }
    for (int o = 16; o; o >>= 1) psum += __shfl_xor_sync(0xffffffffu, psum, o);
    if ((t & 31) == 0) s_red[t >> 5] = psum;
    __syncthreads();                                     // barrier C
    float inv = 1.f / (s_red[0] + s_red[1]);

    // gather: thread t owns cols 8t..8t+7 (uint4 = 8 halfs, LDG.128);
    // depth-4 batch; HFMA2 accumulation flushed to fp32 every 4 neighbors.
    const char* base = ((const char*)g_in_h) + t * 16;
    float4 sa = make_float4(0.f, 0.f, 0.f, 0.f);
    float4 sb = make_float4(0.f, 0.f, 0.f, 0.f);

    int k = 0;
    for (; k + 4 <= nv; k += 4) {
        uint2 e[4];
        uint4 a[4];
        #pragma unroll
        for (int j = 0; j < 4; j++) e[j] = cw[k + j];
        #pragma unroll
        for (int j = 0; j < 4; j++) a[j] = *(const uint4*)(base + e[j].x);
        __half2 h0 = __float2half2_rn(0.f), h1 = h0, h2 = h0, h3 = h0;
        #pragma unroll
        for (int j = 0; j < 4; j++) {
            __half2 w2 = *(__half2*)&e[j].y;
            h0 = __hfma2(w2, *(__half2*)&a[j].x, h0);
            h1 = __hfma2(w2, *(__half2*)&a[j].y, h1);
            h2 = __hfma2(w2, *(__half2*)&a[j].z, h2);
            h3 = __hfma2(w2, *(__half2*)&a[j].w, h3);
        }
        float2 f0 = __half22float2(h0), f1 = __half22float2(h1);
        float2 f2 = __half22float2(h2), f3 = __half22float2(h3);
        sa.x += f0.x; sa.y += f0.y; sa.z += f1.x; sa.w += f1.y;
        sb.x += f2.x; sb.y += f2.y; sb.z += f3.x; sb.w += f3.y;
    }
    for (; k < nv; k++) {           // tail: fp32 path (w already half-quantized)
        uint2 ee = cw[k];
        uint4 aa = *(const uint4*)(base + ee.x);
        float w = __low2float(*(__half2*)&ee.y);
        float2 f0 = __half22float2(*(__half2*)&aa.x);
        float2 f1 = __half22float2(*(__half2*)&aa.y);
        float2 f2 = __half22float2(*(__half2*)&aa.z);
        float2 f3 = __half22float2(*(__half2*)&aa.w);
        sa.x += w * f0.x; sa.y += w * f0.y; sa.z += w * f1.x; sa.w += w * f1.y;
        sb.x += w * f2.x; sb.y += w * f2.y; sb.z += w * f3.x; sb.w += w * f3.y;
    }

    // normalize, add bias, elu (alpha=1)
    float4 bva = __ldg(((const float4*)bias) + 2 * t);
    float4 bvb = __ldg(((const float4*)bias) + 2 * t + 1);
    float4 oa, ob;
    oa.x = fmaf(sa.x, inv, bva.x); oa.y = fmaf(sa.y, inv, bva.y);
    oa.z = fmaf(sa.z, inv, bva.z); oa.w = fmaf(sa.w, inv, bva.w);
    ob.x = fmaf(sb.x, inv, bvb.x); ob.y = fmaf(sb.y, inv, bvb.y);
    ob.z = fmaf(sb.z, inv, bvb.z); ob.w = fmaf(sb.w, inv, bvb.w);
    oa.x = oa.x > 0.f ? oa.x : expm1f(oa.x);
    oa.y = oa.y > 0.f ? oa.y : expm1f(oa.y);
    oa.z = oa.z > 0.f ? oa.z : expm1f(oa.z);
    oa.w = oa.w > 0.f ? oa.w : expm1f(oa.w);
    ob.x = ob.x > 0.f ? ob.x : expm1f(ob.x);
    ob.y = ob.y > 0.f ? ob.y : expm1f(ob.y);
    ob.z = ob.z > 0.f ? ob.z : expm1f(ob.z);
    ob.w = ob.w > 0.f ? ob.w : expm1f(ob.w);
    ((float4*)out)[row * 128 + 2 * t]     = oa;
    ((float4*)out)[row * 128 + 2 * t + 1] = ob;
}

// ---------------- launch ----------------
extern "C" void kernel_launch(void* const* d_in, const int* in_sizes, int n_in,
                              void* d_out, int out_size) {
    const float* input = (const float*)d_in[0];   // [4096, 512]
    const float* rel   = (const float*)d_in[1];   // [474, 500]
    const float* w_rel = (const float*)d_in[3];   // [500]
    const float* bias  = (const float*)d_in[4];   // [512]
    const void*  esrc  = d_in[5];
    const void*  edst  = d_in[6];
    const void*  ridx  = d_in[8];
    float* out = (float*)d_out;

    k_init<<<INIT_BLOCKS, 256>>>(rel, w_rel, esrc, input);
    k_scatter<<<SCAT_BLOCKS, 256>>>(esrc, edst, ridx);
    k_row<<<N_NODES, 64>>>(bias, out);
}